// round 7
// baseline (speedup 1.0000x reference)
#include <cuda_runtime.h>
#include <cstdint>

// WinnerTakesAll: per-batch top-64 mask. x: (32,32,256,256) fp32.
// v6 (resubmit after infra failure): all plain loads/stores.
//   S: sampled threshold (coalesced prefix)     ~7us
//   Z: pure zero stream (proven 39us pattern)
//   C: pure read scan -> candidates             (read stream)
//   M: histogram merge -> scatter 64 winners    ~12us

#define BATCHES 32
#define N_PER   2097152
#define N4      (N_PER / 4)            // 524288 float4 per batch

// --- sampling ---
#define TPB_S   1024
#define SAMP4   8192                   // contiguous float4 prefix per batch
#define SAMP_PER_T (SAMP4 / TPB_S)     // 8
#define SRANK   64

// --- scan ---
#define TPB_A   256
#define VPT4    4
#define CHUNK4  (TPB_A * VPT4)         // 1024 float4 per block
#define BPB     (N4 / CHUNK4)          // 512 blocks per batch
#define CAP     65536                  // per-batch candidate capacity

// --- merge ---
#define TPB_M   512
#define NBINS   4096
#define MAXS    2048

__device__ unsigned long long g_cand[BATCHES][CAP];
__device__ int g_cnt[BATCHES];         // zero-init; merge restores to 0
__device__ int g_bin[BATCHES];

__device__ __forceinline__ unsigned key32(float v) {
    unsigned u = __float_as_uint(v);
    return (u & 0x80000000u) ? ~u : (u | 0x80000000u);  // order-preserving
}
__device__ __forceinline__ float unkey(unsigned k) {
    return (k & 0x80000000u) ? __uint_as_float(k & 0x7fffffffu)
                             : __uint_as_float(~k);
}

// ---------------------------------------------------------------------------
// Kernel S: threshold from contiguous 32768-element sample per batch.
// >=SRANK real elements >= bin floor => top-64 subset of {x >= Tf}.
// ---------------------------------------------------------------------------
__global__ void __launch_bounds__(TPB_S)
sample_kernel(const float4* __restrict__ x4) {
    __shared__ int hist[NBINS];
    __shared__ int s_wsum[TPB_S / 32];
    __shared__ int s_woff[TPB_S / 32];

    const int t = threadIdx.x, lane = t & 31, warp = t >> 5;
    const int batch = blockIdx.x;

    for (int i = t; i < NBINS; i += TPB_S) hist[i] = 0;
    __syncthreads();

    const float4* xb = x4 + (size_t)batch * N4;
    float4 v[SAMP_PER_T];
#pragma unroll
    for (int k = 0; k < SAMP_PER_T; k++)
        v[k] = xb[k * TPB_S + t];
#pragma unroll
    for (int k = 0; k < SAMP_PER_T; k++) {
        atomicAdd(&hist[key32(v[k].x) >> 20], 1);
        atomicAdd(&hist[key32(v[k].y) >> 20], 1);
        atomicAdd(&hist[key32(v[k].z) >> 20], 1);
        atomicAdd(&hist[key32(v[k].w) >> 20], 1);
    }
    __syncthreads();

    int local = 0;
#pragma unroll
    for (int i = 0; i < 4; i++) local += hist[t * 4 + i];
    int suf = local;
#pragma unroll
    for (int off = 1; off < 32; off <<= 1) {
        int o = __shfl_down_sync(0xffffffffu, suf, off);
        if (lane + off < 32) suf += o;
    }
    if (lane == 0) s_wsum[warp] = suf;
    __syncthreads();
    if (warp == 0) {
        int wv = s_wsum[lane], ws = wv;
#pragma unroll
        for (int off = 1; off < 32; off <<= 1) {
            int o = __shfl_down_sync(0xffffffffu, ws, off);
            if (lane + off < 32) ws += o;
        }
        s_woff[lane] = ws - wv;
    }
    __syncthreads();

    int suffix = suf + s_woff[warp];
    int above  = suffix - local;
    if (suffix >= SRANK && above < SRANK) {
        int c = above, b = t * 4;
        for (int bin = t * 4 + 3; bin >= t * 4; bin--) {
            c += hist[bin];
            if (c >= SRANK) { b = bin; break; }
        }
        g_bin[batch] = b;
    }
}

// ---------------------------------------------------------------------------
// Kernel Z: pure zero stream (identical to the measured-66%-DRAM pattern).
// ---------------------------------------------------------------------------
__global__ void zero_kernel(float4* __restrict__ out, int n4) {
    int i = blockIdx.x * blockDim.x + threadIdx.x;
    int stride = gridDim.x * blockDim.x;
    float4 z = make_float4(0.f, 0.f, 0.f, 0.f);
    for (; i < n4; i += stride) out[i] = z;
}

// ---------------------------------------------------------------------------
// Kernel C: pure read scan. Plain loads; candidates to global buffer.
// ---------------------------------------------------------------------------
__global__ void __launch_bounds__(TPB_A)
scan_kernel(const float4* __restrict__ x4) {
    const int t = threadIdx.x, lane = t & 31;
    const int batch = blockIdx.y, blk = blockIdx.x;

    const int bin = g_bin[batch];
    const float Tf = (bin < 8) ? __int_as_float(0xff800000)
                               : unkey((unsigned)bin << 20);

    const size_t base4 = (size_t)batch * N4 + (size_t)blk * CHUNK4;
    const unsigned ebase = (unsigned)(blk * CHUNK4) * 4u;

    float4 v[VPT4];
#pragma unroll
    for (int i = 0; i < VPT4; i++)
        v[i] = x4[base4 + i * TPB_A + t];

#pragma unroll
    for (int i = 0; i < VPT4; i++) {
        float m4 = fmaxf(fmaxf(v[i].x, v[i].y), fmaxf(v[i].z, v[i].w));
        if (__ballot_sync(0xffffffffu, m4 >= Tf)) {
            float vv[4] = {v[i].x, v[i].y, v[i].z, v[i].w};
#pragma unroll
            for (int c = 0; c < 4; c++) {
                bool pred = (vv[c] >= Tf);
                unsigned m = __ballot_sync(0xffffffffu, pred);
                if (m) {
                    int leader = __ffs(m) - 1;
                    int pos = 0;
                    if (lane == leader)
                        pos = atomicAdd(&g_cnt[batch], __popc(m));
                    pos = __shfl_sync(0xffffffffu, pos, leader);
                    if (pred) {
                        int my = pos + __popc(m & ((1u << lane) - 1u));
                        if (my < CAP) {
                            unsigned e = ebase + (unsigned)(i * TPB_A + t) * 4u + (unsigned)c;
                            g_cand[batch][my] =
                                ((unsigned long long)key32(vv[c]) << 32) | (unsigned)(~e);
                        }
                    }
                }
            }
        }
    }
}

// ---------------------------------------------------------------------------
// Kernel M: per-batch exact top-64 from candidates; scatter; reset counter.
// ---------------------------------------------------------------------------
__global__ void __launch_bounds__(TPB_M)
merge_kernel(const float* __restrict__ x, float* __restrict__ out) {
    __shared__ int hist[NBINS];
    __shared__ int s_wsum[TPB_M / 32];
    __shared__ int s_woff[TPB_M / 32];
    __shared__ unsigned long long s_surv[MAXS];
    __shared__ int s_scnt;
    __shared__ unsigned s_bin;
    __shared__ int s_tot;

    const int t = threadIdx.x, lane = t & 31, warp = t >> 5;
    const int batch = blockIdx.x;
    const int raw = g_cnt[batch];
    const int cnt = min(raw, CAP);

    if (t == 0) s_scnt = 0;

    if (raw <= CAP) {
        for (int i = t; i < NBINS; i += TPB_M) hist[i] = 0;
        __syncthreads();
        for (int i = t; i < cnt; i += TPB_M)
            atomicAdd(&hist[(unsigned)(g_cand[batch][i] >> 52)], 1);
        __syncthreads();

        int local = 0;
#pragma unroll
        for (int i = 0; i < 8; i++) local += hist[t * 8 + i];
        int suf = local;
#pragma unroll
        for (int off = 1; off < 32; off <<= 1) {
            int o = __shfl_down_sync(0xffffffffu, suf, off);
            if (lane + off < 32) suf += o;
        }
        if (lane == 0) s_wsum[warp] = suf;
        __syncthreads();
        if (warp == 0 && lane < TPB_M / 32) {
            int wv = s_wsum[lane], ws = wv;
#pragma unroll
            for (int off = 1; off < TPB_M / 32; off <<= 1) {
                int o = __shfl_down_sync(0xffffu, ws, off);
                if (lane + off < TPB_M / 32) ws += o;
            }
            s_woff[lane] = ws - wv;
        }
        __syncthreads();
        int suffix = suf + s_woff[warp];
        int above  = suffix - local;
        if (suffix >= 64 && above < 64) {
            int c = above, b = t * 8;
            for (int bin = t * 8 + 7; bin >= t * 8; bin--) {
                c += hist[bin];
                if (c >= 64) { b = bin; break; }
            }
            s_bin = (unsigned)b;
        }
        __syncthreads();
        const unsigned bthr = s_bin;

        for (int i = t; i < cnt; i += TPB_M) {
            unsigned long long ck = g_cand[batch][i];
            if ((unsigned)(ck >> 52) >= bthr) {
                int p = atomicAdd(&s_scnt, 1);
                if (p < MAXS) s_surv[p] = ck;
            }
        }
        __syncthreads();
    } else {
        // Fallback (CAP overflow only): exact bitwise threshold over x.
        __syncthreads();
        const float* xb = x + (size_t)batch * N_PER;
        unsigned T = 0;
        for (int bit = 31; bit >= 0; bit--) {
            unsigned candT = T | (1u << bit);
            int c = 0;
            for (int i = t; i < N_PER; i += TPB_M) c += (key32(xb[i]) >= candT);
#pragma unroll
            for (int o = 16; o > 0; o >>= 1) c += __shfl_xor_sync(0xffffffffu, c, o);
            if (lane == 0) s_wsum[warp] = c;
            __syncthreads();
            if (t == 0) {
                int tot = 0;
                for (int w = 0; w < TPB_M / 32; w++) tot += s_wsum[w];
                s_tot = tot;
            }
            __syncthreads();
            if (s_tot >= 64) T = candT;
            __syncthreads();
        }
        for (int i = t; i < N_PER; i += TPB_M) {
            unsigned u = key32(xb[i]);
            if (u >= T) {
                int p = atomicAdd(&s_scnt, 1);
                if (p < MAXS)
                    s_surv[p] = ((unsigned long long)u << 32) | (unsigned)(~i);
            }
        }
        __syncthreads();
    }

    const int S = min(s_scnt, MAXS);
    if (t < S) {
        unsigned long long me = s_surv[t];
        int r = 0;
        for (int j = 0; j < S; j++) r += (s_surv[j] > me);
        if (r < 64) {
            unsigned idx = ~((unsigned)me);
            out[(size_t)batch * N_PER + idx] = unkey((unsigned)(me >> 32));
        }
    }
    __syncthreads();
    if (t == 0) g_cnt[batch] = 0;
}

// ---------------------------------------------------------------------------
extern "C" void kernel_launch(void* const* d_in, const int* in_sizes, int n_in,
                              void* d_out, int out_size) {
    const float* x = (const float*)d_in[0];
    float* out = (float*)d_out;

    sample_kernel<<<BATCHES, TPB_S>>>((const float4*)x);

    zero_kernel<<<4096, 256>>>((float4*)out, out_size / 4);

    dim3 gC(BPB, BATCHES);
    scan_kernel<<<gC, TPB_A>>>((const float4*)x);

    merge_kernel<<<BATCHES, TPB_M>>>(x, out);
}

// round 8
// speedup vs baseline: 1.0933x; 1.0933x over previous
#include <cuda_runtime.h>
#include <cstdint>

// WinnerTakesAll: per-batch top-64 mask. x: (32,32,256,256) fp32.
// v8: streaming read moved to cp.async.bulk (UBLKCP) -> smem, processed via
// LDS; zero-write fused into the same kernel. Sampler + merge unchanged.

#define BATCHES 32
#define N_PER   2097152
#define N4      (N_PER / 4)

// --- sampling ---
#define TPB_S   1024
#define SAMP4   8192
#define SAMP_PER_T (SAMP4 / TPB_S)
#define SRANK   64

// --- fused scan ---
#define TPB_F   256
#define TILE_B  16384                    // bytes per tile (4096 floats)
#define TILE_F  (TILE_B / 4)             // 4096 floats
#define TILE_F4 (TILE_B / 16)            // 1024 float4
#define F4PT    (TILE_F4 / TPB_F)        // 4 float4 per thread per tile
#define NTILES  8
#define CHUNK_ELEMS (NTILES * TILE_F)    // 32768 elements per block
#define BPB_F   (N_PER / CHUNK_ELEMS)    // 64 blocks per batch
#define CAP     65536

// --- merge ---
#define TPB_M   512
#define NBINS   4096
#define MAXS    2048

__device__ unsigned long long g_cand[BATCHES][CAP];
__device__ int g_cnt[BATCHES];           // zero-init; merge restores to 0
__device__ int g_bin[BATCHES];

__device__ __forceinline__ unsigned key32(float v) {
    unsigned u = __float_as_uint(v);
    return (u & 0x80000000u) ? ~u : (u | 0x80000000u);
}
__device__ __forceinline__ float unkey(unsigned k) {
    return (k & 0x80000000u) ? __uint_as_float(k & 0x7fffffffu)
                             : __uint_as_float(~k);
}
__device__ __forceinline__ unsigned smem_u32(const void* p) {
    unsigned a;
    asm("{ .reg .u64 t; cvta.to.shared.u64 t, %1; cvt.u32.u64 %0, t; }"
        : "=r"(a) : "l"(p));
    return a;
}
__device__ __forceinline__ void mbar_init(unsigned a, unsigned c) {
    asm volatile("mbarrier.init.shared.b64 [%0], %1;" :: "r"(a), "r"(c) : "memory");
}
__device__ __forceinline__ void mbar_expect(unsigned a, unsigned bytes) {
    asm volatile("mbarrier.arrive.expect_tx.shared.b64 _, [%0], %1;"
                 :: "r"(a), "r"(bytes) : "memory");
}
__device__ __forceinline__ void mbar_wait(unsigned a, unsigned parity) {
    asm volatile(
        "{\n\t"
        ".reg .pred P;\n\t"
        "W_%=:\n\t"
        "mbarrier.try_wait.parity.acquire.cta.shared::cta.b64 P, [%0], %1, 0x989680;\n\t"
        "@P bra.uni D_%=;\n\t"
        "bra.uni W_%=;\n\t"
        "D_%=:\n\t"
        "}" :: "r"(a), "r"(parity) : "memory");
}
__device__ __forceinline__ void bulk_g2s(unsigned dst, const void* src,
                                         unsigned bytes, unsigned mbar) {
    asm volatile(
        "cp.async.bulk.shared::cluster.global.mbarrier::complete_tx::bytes "
        "[%0], [%1], %2, [%3];"
        :: "r"(dst), "l"(src), "r"(bytes), "r"(mbar) : "memory");
}

// ---------------------------------------------------------------------------
// Kernel S: sampled threshold (unchanged from R7; proven 6.6us, guarantee:
// >=SRANK real elements >= bin floor => top-64 subset of candidates).
// ---------------------------------------------------------------------------
__global__ void __launch_bounds__(TPB_S)
sample_kernel(const float4* __restrict__ x4) {
    __shared__ int hist[NBINS];
    __shared__ int s_wsum[TPB_S / 32];
    __shared__ int s_woff[TPB_S / 32];

    const int t = threadIdx.x, lane = t & 31, warp = t >> 5;
    const int batch = blockIdx.x;

    for (int i = t; i < NBINS; i += TPB_S) hist[i] = 0;
    __syncthreads();

    const float4* xb = x4 + (size_t)batch * N4;
    float4 v[SAMP_PER_T];
#pragma unroll
    for (int k = 0; k < SAMP_PER_T; k++)
        v[k] = xb[k * TPB_S + t];
#pragma unroll
    for (int k = 0; k < SAMP_PER_T; k++) {
        atomicAdd(&hist[key32(v[k].x) >> 20], 1);
        atomicAdd(&hist[key32(v[k].y) >> 20], 1);
        atomicAdd(&hist[key32(v[k].z) >> 20], 1);
        atomicAdd(&hist[key32(v[k].w) >> 20], 1);
    }
    __syncthreads();

    int local = 0;
#pragma unroll
    for (int i = 0; i < 4; i++) local += hist[t * 4 + i];
    int suf = local;
#pragma unroll
    for (int off = 1; off < 32; off <<= 1) {
        int o = __shfl_down_sync(0xffffffffu, suf, off);
        if (lane + off < 32) suf += o;
    }
    if (lane == 0) s_wsum[warp] = suf;
    __syncthreads();
    if (warp == 0) {
        int wv = s_wsum[lane], ws = wv;
#pragma unroll
        for (int off = 1; off < 32; off <<= 1) {
            int o = __shfl_down_sync(0xffffffffu, ws, off);
            if (lane + off < 32) ws += o;
        }
        s_woff[lane] = ws - wv;
    }
    __syncthreads();

    int suffix = suf + s_woff[warp];
    int above  = suffix - local;
    if (suffix >= SRANK && above < SRANK) {
        int c = above, b = t * 4;
        for (int bin = t * 4 + 3; bin >= t * 4; bin--) {
            c += hist[bin];
            if (c >= SRANK) { b = bin; break; }
        }
        g_bin[batch] = b;
    }
}

// ---------------------------------------------------------------------------
// Kernel F: fused bulk-async scan + zero-write.
//   Double-buffered cp.async.bulk 16KB tiles; zero stores issued in the
//   load's latency shadow; candidate emit is rare per-thread atomics.
// ---------------------------------------------------------------------------
__global__ void __launch_bounds__(TPB_F)
fused_kernel(const float* __restrict__ x, float* __restrict__ out) {
    __shared__ __align__(128) float4 buf[2][TILE_F4];   // 32 KiB
    __shared__ __align__(8) unsigned long long mbar_s[2];

    const int t = threadIdx.x;
    const int batch = blockIdx.y, blk = blockIdx.x;

    const int bin = g_bin[batch];
    const float Tf = (bin < 8) ? __int_as_float(0xff800000)
                               : unkey((unsigned)bin << 20);

    const size_t baseE = (size_t)batch * N_PER + (size_t)blk * CHUNK_ELEMS;
    const float* xbase = x + baseE;
    float4* obase = (float4*)(out + baseE);
    const unsigned ebase = (unsigned)(blk * CHUNK_ELEMS);

    const unsigned mb = smem_u32(&mbar_s[0]);
    const unsigned sb0 = smem_u32(&buf[0][0]);
    const unsigned sb1 = smem_u32(&buf[1][0]);

    if (t == 0) {
        mbar_init(mb, 1);
        mbar_init(mb + 8, 1);
        // fence: make inits visible to the async proxy before first bulk
        asm volatile("fence.proxy.async.shared::cta;" ::: "memory");
        mbar_expect(mb, TILE_B);
        bulk_g2s(sb0, xbase, TILE_B, mb);
        mbar_expect(mb + 8, TILE_B);
        bulk_g2s(sb1, xbase + TILE_F, TILE_B, mb + 8);
    }
    __syncthreads();

    const float4 z = make_float4(0.f, 0.f, 0.f, 0.f);

    for (int j = 0; j < NTILES; j++) {
        const int s = j & 1;

        // Zero-write tile j's output region while its load is in flight.
#pragma unroll
        for (int i = 0; i < F4PT; i++)
            obase[j * TILE_F4 + i * TPB_F + t] = z;

        mbar_wait(mb + 8 * s, (unsigned)((j >> 1) & 1));

        // Process 4 float4 from smem (conflict-free LDS.128).
#pragma unroll
        for (int i = 0; i < F4PT; i++) {
            float4 v = buf[s][i * TPB_F + t];
            float m4 = fmaxf(fmaxf(v.x, v.y), fmaxf(v.z, v.w));
            if (m4 >= Tf) {                               // ~6.5% of threads/tile
                unsigned e0 = ebase + (unsigned)(j * TILE_F + (i * TPB_F + t) * 4);
                float vv[4] = {v.x, v.y, v.z, v.w};
#pragma unroll
                for (int c = 0; c < 4; c++) {
                    if (vv[c] >= Tf) {
                        int pos = atomicAdd(&g_cnt[batch], 1);
                        if (pos < CAP)
                            g_cand[batch][pos] =
                                ((unsigned long long)key32(vv[c]) << 32) |
                                (unsigned)(~(e0 + (unsigned)c));
                    }
                }
            }
        }
        __syncthreads();   // all consumers done with buf[s]

        if (t == 0 && j + 2 < NTILES) {
            mbar_expect(mb + 8 * s, TILE_B);
            bulk_g2s(s ? sb1 : sb0, xbase + (size_t)(j + 2) * TILE_F, TILE_B,
                     mb + 8 * s);
        }
    }
}

// ---------------------------------------------------------------------------
// Kernel M: per-batch exact top-64 (unchanged from R7); scatter; reset cnt.
// ---------------------------------------------------------------------------
__global__ void __launch_bounds__(TPB_M)
merge_kernel(const float* __restrict__ x, float* __restrict__ out) {
    __shared__ int hist[NBINS];
    __shared__ int s_wsum[TPB_M / 32];
    __shared__ int s_woff[TPB_M / 32];
    __shared__ unsigned long long s_surv[MAXS];
    __shared__ int s_scnt;
    __shared__ unsigned s_bin;
    __shared__ int s_tot;

    const int t = threadIdx.x, lane = t & 31, warp = t >> 5;
    const int batch = blockIdx.x;
    const int raw = g_cnt[batch];
    const int cnt = min(raw, CAP);

    if (t == 0) s_scnt = 0;

    if (raw <= CAP) {
        for (int i = t; i < NBINS; i += TPB_M) hist[i] = 0;
        __syncthreads();
        for (int i = t; i < cnt; i += TPB_M)
            atomicAdd(&hist[(unsigned)(g_cand[batch][i] >> 52)], 1);
        __syncthreads();

        int local = 0;
#pragma unroll
        for (int i = 0; i < 8; i++) local += hist[t * 8 + i];
        int suf = local;
#pragma unroll
        for (int off = 1; off < 32; off <<= 1) {
            int o = __shfl_down_sync(0xffffffffu, suf, off);
            if (lane + off < 32) suf += o;
        }
        if (lane == 0) s_wsum[warp] = suf;
        __syncthreads();
        if (warp == 0 && lane < TPB_M / 32) {
            int wv = s_wsum[lane], ws = wv;
#pragma unroll
            for (int off = 1; off < TPB_M / 32; off <<= 1) {
                int o = __shfl_down_sync(0xffffu, ws, off);
                if (lane + off < TPB_M / 32) ws += o;
            }
            s_woff[lane] = ws - wv;
        }
        __syncthreads();
        int suffix = suf + s_woff[warp];
        int above  = suffix - local;
        if (suffix >= 64 && above < 64) {
            int c = above, b = t * 8;
            for (int bin = t * 8 + 7; bin >= t * 8; bin--) {
                c += hist[bin];
                if (c >= 64) { b = bin; break; }
            }
            s_bin = (unsigned)b;
        }
        __syncthreads();
        const unsigned bthr = s_bin;

        for (int i = t; i < cnt; i += TPB_M) {
            unsigned long long ck = g_cand[batch][i];
            if ((unsigned)(ck >> 52) >= bthr) {
                int p = atomicAdd(&s_scnt, 1);
                if (p < MAXS) s_surv[p] = ck;
            }
        }
        __syncthreads();
    } else {
        // Fallback (CAP overflow only): exact bitwise threshold over x.
        __syncthreads();
        const float* xb = x + (size_t)batch * N_PER;
        unsigned T = 0;
        for (int bit = 31; bit >= 0; bit--) {
            unsigned candT = T | (1u << bit);
            int c = 0;
            for (int i = t; i < N_PER; i += TPB_M) c += (key32(xb[i]) >= candT);
#pragma unroll
            for (int o = 16; o > 0; o >>= 1) c += __shfl_xor_sync(0xffffffffu, c, o);
            if (lane == 0) s_wsum[warp] = c;
            __syncthreads();
            if (t == 0) {
                int tot = 0;
                for (int w = 0; w < TPB_M / 32; w++) tot += s_wsum[w];
                s_tot = tot;
            }
            __syncthreads();
            if (s_tot >= 64) T = candT;
            __syncthreads();
        }
        for (int i = t; i < N_PER; i += TPB_M) {
            unsigned u = key32(xb[i]);
            if (u >= T) {
                int p = atomicAdd(&s_scnt, 1);
                if (p < MAXS)
                    s_surv[p] = ((unsigned long long)u << 32) | (unsigned)(~i);
            }
        }
        __syncthreads();
    }

    const int S = min(s_scnt, MAXS);
    if (t < S) {
        unsigned long long me = s_surv[t];
        int r = 0;
        for (int j = 0; j < S; j++) r += (s_surv[j] > me);
        if (r < 64) {
            unsigned idx = ~((unsigned)me);
            out[(size_t)batch * N_PER + idx] = unkey((unsigned)(me >> 32));
        }
    }
    __syncthreads();
    if (t == 0) g_cnt[batch] = 0;
}

// ---------------------------------------------------------------------------
extern "C" void kernel_launch(void* const* d_in, const int* in_sizes, int n_in,
                              void* d_out, int out_size) {
    const float* x = (const float*)d_in[0];
    float* out = (float*)d_out;

    sample_kernel<<<BATCHES, TPB_S>>>((const float4*)x);

    dim3 gF(BPB_F, BATCHES);
    fused_kernel<<<gF, TPB_F>>>(x, out);

    merge_kernel<<<BATCHES, TPB_M>>>(x, out);
}